// round 16
// baseline (speedup 1.0000x reference)
#include <cuda_runtime.h>
#include <cuda_bf16.h>
#include <cstdint>
#include <cstddef>

#define NROWS 65536
#define EDIM  512
#define NE    1024
#define NQ    4

static constexpr size_t XQ_OFF   = 0;
static constexpr size_t LOSS_OFF = (size_t)NROWS * EDIM;
static constexpr size_t IDX_OFF  = LOSS_OFF + 1;
static constexpr size_t DIST_OFF = IDX_OFF + (size_t)NROWS * NQ;

// -------- scratch (device globals; no runtime allocation) --------
__device__ __nv_bfloat16  g_res_bf[(size_t)NROWS * EDIM];
__device__ __nv_bfloat16  g_cb_bf[(size_t)NQ * NE * EDIM];
__device__ float          g_enorm32[NQ * NE];   // XLA-GPU-emulated fp32 ||e||^2
__device__ float          g_rnorm32[NROWS];     // XLA-GPU-emulated fp32 ||r||^2 (current stage)
__device__ float          g_top2d[(size_t)NROWS * 16];
__device__ int            g_top2i[(size_t)NROWS * 16];
__device__ double         g_loss_arr[NQ * 64];  // spread loss accumulators

// -------- helpers --------
__device__ __forceinline__ uint32_t s2u(const void* p) {
    uint32_t a;
    asm("{ .reg .u64 t; cvta.to.shared.u64 t, %1; cvt.u32.u64 %0, t; }" : "=r"(a) : "l"(p));
    return a;
}
__device__ __forceinline__ void cpa16_cg(uint32_t daddr, const void* src) {
    asm volatile("cp.async.cg.shared.global [%0], [%1], 16;\n" :: "r"(daddr), "l"(src));
}
__device__ __forceinline__ void ldsm4(uint32_t* r, uint32_t addr) {
    asm volatile("ldmatrix.sync.aligned.m8n8.x4.shared.b16 {%0,%1,%2,%3}, [%4];"
                 : "=r"(r[0]), "=r"(r[1]), "=r"(r[2]), "=r"(r[3]) : "r"(addr));
}
__device__ __forceinline__ void mma16816(float* c, const uint32_t* a, uint32_t b0, uint32_t b1) {
    asm volatile("mma.sync.aligned.m16n8k16.row.col.f32.bf16.bf16.f32 "
                 "{%0,%1,%2,%3}, {%4,%5,%6,%7}, {%8,%9}, {%0,%1,%2,%3};"
                 : "+f"(c[0]), "+f"(c[1]), "+f"(c[2]), "+f"(c[3])
                 : "r"(a[0]), "r"(a[1]), "r"(a[2]), "r"(a[3]), "r"(b0), "r"(b1));
}
__device__ __forceinline__ float warp_tree_reduce(float v) {
    v = __fadd_rn(v, __shfl_down_sync(0xffffffffu, v, 16));
    v = __fadd_rn(v, __shfl_down_sync(0xffffffffu, v, 8));
    v = __fadd_rn(v, __shfl_down_sync(0xffffffffu, v, 4));
    v = __fadd_rn(v, __shfl_down_sync(0xffffffffu, v, 2));
    v = __fadd_rn(v, __shfl_down_sync(0xffffffffu, v, 1));
    return v;
}

// =====================================================================
// prep: bf16 copies + norms (residual_0 == x; never materialized in fp32)
// =====================================================================
__global__ void __launch_bounds__(256) prep_kernel(const float* __restrict__ x,
                                                   const float* __restrict__ cb) {
    if (blockIdx.x == 0 && threadIdx.x < NQ * 64) g_loss_arr[threadIdx.x] = 0.0;
    int w = (blockIdx.x * blockDim.x + threadIdx.x) >> 5;
    int lane = threadIdx.x & 31;
    if (w >= NROWS + NQ * NE) return;
    float acc = 0.0f;
    if (w < NROWS) {
        const float* src = x + (size_t)w * EDIM;
        #pragma unroll
        for (int j = 0; j < 16; j++) {
            int off = lane + 32 * j;
            float v = src[off];
            g_res_bf[(size_t)w * EDIM + off] = __float2bfloat16(v);
            acc = __fmaf_rn(v, v, acc);
        }
        acc = warp_tree_reduce(acc);
        if (lane == 0) g_rnorm32[w] = acc;
    } else {
        int c = w - NROWS;
        const float* src = cb + (size_t)c * EDIM;
        #pragma unroll
        for (int j = 0; j < 16; j++) {
            int off = lane + 32 * j;
            float v = src[off];
            g_cb_bf[(size_t)c * EDIM + off] = __float2bfloat16(v);
            acc = __fmaf_rn(v, v, acc);
        }
        acc = warp_tree_reduce(acc);
        if (lane == 0) g_enorm32[c] = acc;
    }
}

// =====================================================================
// mma.sync bf16 GEMM: exact R13/R15 config (byte-identical mainloop+epilogue)
// =====================================================================
#define GM_STG   32768
#define GM_SMEM  98304
#define GM_PITCH 129

__global__ void __launch_bounds__(256, 2) gemm_mma_kernel(int s, int yt0, float* __restrict__ dist) {
    extern __shared__ char smem[];
    const uint32_t sb = s2u(smem);
    const int tid = threadIdx.x, wid = tid >> 5, l = tid & 31;
    const int bn0 = blockIdx.x * 128, bm0 = (blockIdx.y + yt0) * 128;
    const int wm = wid >> 2, wn = wid & 3;           // 2x4 warp grid, 64x32 tiles
    const int mbase = wm * 64, nbase = wn * 32;

    const char* Ag = (const char*)(g_res_bf + (size_t)bm0 * EDIM);
    const char* Bg = (const char*)(g_cb_bf + ((size_t)s * NE + bn0) * EDIM);

    const int frow = l & 15;
    const uint32_t fseg = (uint32_t)(l >> 4) * 16;
    const uint32_t mask = (uint32_t)((l & 7) << 4);

    float acc[4][4][4];
    #pragma unroll
    for (int a = 0; a < 4; a++)
        #pragma unroll
        for (int b = 0; b < 4; b++)
            #pragma unroll
            for (int c = 0; c < 4; c++) acc[a][b][c] = 0.0f;

    auto load_chunk = [&](int kc, int stg) {
        uint32_t abase = sb + (uint32_t)stg * GM_STG;
        uint32_t bbase = abase + 16384;
        #pragma unroll
        for (int it = 0; it < 4; it++) {
            int idx = tid + it * 256;
            int r = idx >> 3, c = idx & 7;
            uint32_t soff = (uint32_t)(r * 128 + ((c ^ (r & 7)) * 16));
            cpa16_cg(abase + soff, Ag + (size_t)r * 1024 + (size_t)kc * 128 + c * 16);
            cpa16_cg(bbase + soff, Bg + (size_t)r * 1024 + (size_t)kc * 128 + c * 16);
        }
        asm volatile("cp.async.commit_group;\n");
    };

    load_chunk(0, 0);
    load_chunk(1, 1);

    for (int c = 0; c < 8; c++) {
        int stg = c % 3;
        if (c < 7) asm volatile("cp.async.wait_group 1;\n" ::: "memory");
        else       asm volatile("cp.async.wait_group 0;\n" ::: "memory");
        __syncthreads();
        if (c + 2 < 8) load_chunk(c + 2, (c + 2) % 3);

        uint32_t abase = sb + (uint32_t)stg * GM_STG;
        uint32_t bbase = abase + 16384;
        #pragma unroll
        for (int kk = 0; kk < 4; kk++) {
            uint32_t af[4][4], bf[2][4];
            #pragma unroll
            for (int t = 0; t < 4; t++)
                ldsm4(af[t], abase + (uint32_t)((mbase + t * 16 + frow) * 128)
                              + (((uint32_t)(kk * 32) + fseg) ^ mask));
            #pragma unroll
            for (int p = 0; p < 2; p++)
                ldsm4(bf[p], bbase + (uint32_t)((nbase + p * 16 + frow) * 128)
                              + (((uint32_t)(kk * 32) + fseg) ^ mask));
            #pragma unroll
            for (int tm = 0; tm < 4; tm++)
                #pragma unroll
                for (int p = 0; p < 2; p++) {
                    mma16816(acc[tm][2 * p],     af[tm], bf[p][0], bf[p][2]);
                    mma16816(acc[tm][2 * p + 1], af[tm], bf[p][1], bf[p][3]);
                }
        }
    }
    __syncthreads();

    // ---- single-pass epilogue (exact R13) ----
    float* stage = (float*)smem;                        // 128 x 129 floats (66048 B)
    float* ens   = (float*)(smem + 66048);              // 128 e-norms
    float* rns   = (float*)(smem + 66560);              // 128 r-norms
    float* pd1   = (float*)(smem + 67072);              // 256 partial top-2
    float* pd2   = (float*)(smem + 68096);
    int*   pi1   = (int*)  (smem + 69120);
    int*   pi2   = (int*)  (smem + 70144);
    if (tid < 128) {
        ens[tid] = g_enorm32[s * NE + bn0 + tid];
        rns[tid] = g_rnorm32[bm0 + tid];
    }
    __syncthreads();

    #pragma unroll
    for (int tm = 0; tm < 4; tm++) {
        int r0 = mbase + tm * 16 + (l >> 2);
        float rnA = rns[r0];
        float rnB = rns[r0 + 8];
        #pragma unroll
        for (int tn = 0; tn < 4; tn++) {
            int c0 = nbase + tn * 8 + (l & 3) * 2;
            float e0 = ens[c0], e1 = ens[c0 + 1];
            float* a = acc[tm][tn];
            stage[r0 * GM_PITCH + c0]           = __fadd_rn(__fsub_rn(rnA, __fmul_rn(2.0f, a[0])), e0);
            stage[r0 * GM_PITCH + c0 + 1]       = __fadd_rn(__fsub_rn(rnA, __fmul_rn(2.0f, a[1])), e1);
            stage[(r0 + 8) * GM_PITCH + c0]     = __fadd_rn(__fsub_rn(rnB, __fmul_rn(2.0f, a[2])), e0);
            stage[(r0 + 8) * GM_PITCH + c0 + 1] = __fadd_rn(__fsub_rn(rnB, __fmul_rn(2.0f, a[3])), e1);
        }
    }
    __syncthreads();

    {
        int row = tid & 127, half = tid >> 7;
        float d1 = 3.4e38f, d2 = 3.4e38f; int i1 = 0x7fffffff, i2 = 0x7fffffff;
        int cbase = half * 64;
        #pragma unroll 8
        for (int j = 0; j < 64; j++) {
            float d = stage[row * GM_PITCH + cbase + j];
            int gi = bn0 + cbase + j;
            if (d < d1)      { d2 = d1; i2 = i1; d1 = d; i1 = gi; }
            else if (d < d2) { d2 = d; i2 = gi; }
        }
        pd1[tid] = d1; pd2[tid] = d2; pi1[tid] = i1; pi2[tid] = i2;
    }
    __syncthreads();
    if (tid < 128) {
        float d1a = pd1[tid], d2a = pd2[tid];       int i1a = pi1[tid], i2a = pi2[tid];
        float d1b = pd1[tid + 128], d2b = pd2[tid + 128]; int i1b = pi1[tid + 128], i2b = pi2[tid + 128];
        float m1, m2; int mi1, mi2;
        if (d1b < d1a) {
            m1 = d1b; mi1 = i1b;
            if (d1a <= d2b) { m2 = d1a; mi2 = i1a; } else { m2 = d2b; mi2 = i2b; }
        } else {
            m1 = d1a; mi1 = i1a;
            if (d2a <= d1b) { m2 = d2a; mi2 = i2a; } else { m2 = d1b; mi2 = i1b; }
        }
        int rowG = bm0 + tid;
        size_t tb = ((size_t)rowG * 8 + blockIdx.x) * 2;
        g_top2d[tb] = m1;     g_top2i[tb] = mi1;
        g_top2d[tb + 1] = m2; g_top2i[tb + 1] = mi2;
    }
    {
        int rh = tid >> 7, col = tid & 127;
        #pragma unroll 8
        for (int it = 0; it < 64; it++) {
            int r = it * 2 + rh;
            dist[(size_t)(bm0 + r) * (NQ * NE) + (size_t)s * NE + bn0 + col] =
                stage[r * GM_PITCH + col];
        }
    }
}

// =====================================================================
// update: residual recomputed from x + previous indices (bitwise chain),
// staged in smem; fp32 residual array eliminated. Regs capped at 32.
// =====================================================================
#define MARGIN 1.25f
#define CANDMAX 32

__global__ void __launch_bounds__(256, 8) update_kernel(int s, int n0, const float* __restrict__ x,
                                                        const float* __restrict__ cb,
                                                        float* __restrict__ out) {
    __shared__ float s_row[8][EDIM];     // 16 KB: recomputed residual rows
    __shared__ int s_cand[8][CANDMAX];
    __shared__ double s_ls[8];
    const int w = threadIdx.x >> 5, lane = threadIdx.x & 31;
    const int n = n0 + blockIdx.x * 8 + w;
    const unsigned FULL = 0xffffffffu;

    // ---- recompute residual r_s from x and idx_0..idx_{s-1} (bitwise chain) ----
    {
        const float* ep0 = nullptr; const float* ep1 = nullptr; const float* ep2 = nullptr;
        if (s > 0) ep0 = cb + ((size_t)0 * NE + (int)out[IDX_OFF + (size_t)n * NQ + 0]) * EDIM;
        if (s > 1) ep1 = cb + ((size_t)1 * NE + (int)out[IDX_OFF + (size_t)n * NQ + 1]) * EDIM;
        if (s > 2) ep2 = cb + ((size_t)2 * NE + (int)out[IDX_OFF + (size_t)n * NQ + 2]) * EDIM;
        const float* xr = x + (size_t)n * EDIM;
        #pragma unroll 4
        for (int j = 0; j < 16; j++) {
            int off = lane + 32 * j;
            float r = xr[off];
            if (s > 0) { float e = ep0[off]; float u = __fsub_rn(e, r); float q = __fadd_rn(r, u); r = __fsub_rn(r, q); }
            if (s > 1) { float e = ep1[off]; float u = __fsub_rn(e, r); float q = __fadd_rn(r, u); r = __fsub_rn(r, q); }
            if (s > 2) { float e = ep2[off]; float u = __fsub_rn(e, r); float q = __fadd_rn(r, u); r = __fsub_rn(r, q); }
            s_row[w][off] = r;
        }
    }
    __syncwarp();
    const float* rrow = s_row[w];

    float myd = 3.4e38f; int myi = 0x7fffffff;
    if (lane < 16) { myd = g_top2d[(size_t)n * 16 + lane]; myi = g_top2i[(size_t)n * 16 + lane]; }
    float bd = myd; int bi = myi;
    #pragma unroll
    for (int off = 16; off; off >>= 1) {
        float od = __shfl_xor_sync(FULL, bd, off);
        int   oi = __shfl_xor_sync(FULL, bi, off);
        if (od < bd || (od == bd && oi < bi)) { bd = od; bi = oi; }
    }
    float thr = bd + MARGIN;

    int partner = (lane & 30) | 1;
    float d2b = __shfl_sync(FULL, myd, partner);
    bool block_rescan = (d2b <= thr);
    bool take = (lane < 16) && (myd <= thr) && !block_rescan;
    unsigned tm = __ballot_sync(FULL, take);
    int cnt = __popc(tm);
    if (take) s_cand[w][__popc(tm & ((1u << lane) - 1u))] = myi;

    unsigned rb = __ballot_sync(FULL, (lane < 16) && ((lane & 1) == 1) && (myd <= thr));
    const float* dist = out + DIST_OFF;
    size_t rowbase = (size_t)n * (NQ * NE) + (size_t)s * NE;
    while (rb) {
        int L = __ffs(rb) - 1; rb &= rb - 1;
        int b = L >> 1;
        #pragma unroll
        for (int j = 0; j < 4; j++) {
            int c = b * 128 + lane + 32 * j;
            float dv = dist[rowbase + c];
            bool t2 = (dv <= thr);
            unsigned m2 = __ballot_sync(FULL, t2);
            if (t2) {
                int pos = cnt + __popc(m2 & ((1u << lane) - 1u));
                if (pos < CANDMAX) s_cand[w][pos] = c;
            }
            cnt += __popc(m2);
        }
    }
    if (cnt > CANDMAX) cnt = CANDMAX;
    __syncwarp();

    int chosen;
    if (cnt == 1) {
        chosen = bi;
    } else {
        float a = g_rnorm32[n];
        int myc = (lane < cnt) ? s_cand[w][lane] : -1;
        float dmy = 3.4e38f;
        if (myc >= 0) {
            const float* e = cb + ((size_t)s * NE + myc) * EDIM;
            float b = 0.0f;
            for (int k = 0; k < EDIM; k++) b = __fmaf_rn(rrow[k], e[k], b);
            dmy = __fadd_rn(__fsub_rn(a, __fmul_rn(2.0f, b)), g_enorm32[s * NE + myc]);
        }
        float cbd = dmy; int cbi = (myc >= 0) ? myc : 0x7fffffff;
        #pragma unroll
        for (int off = 16; off; off >>= 1) {
            float od = __shfl_xor_sync(FULL, cbd, off);
            int   oi = __shfl_xor_sync(FULL, cbi, off);
            if (od < cbd || (od == cbd && oi < cbi)) { cbd = od; cbi = oi; }
        }
        chosen = cbi;
    }
    if (lane == 0) out[IDX_OFF + (size_t)n * NQ + s] = (float)chosen;

    const float* e = cb + ((size_t)s * NE + chosen) * EDIM;
    double lsum = 0.0;
    float racc = 0.0f;
    #pragma unroll 4
    for (int j = 0; j < 16; j++) {
        int off = lane + 32 * j;
        float r  = rrow[off];
        float ev = e[off];
        float u     = __fsub_rn(ev, r);      // xq - residual
        float xq_st = __fadd_rn(r, u);       // residual + (xq - residual)
        float rn_   = __fsub_rn(r, xq_st);   // new residual
        lsum += (double)u * (double)u;
        if (s < 3) {
            g_res_bf[(size_t)n * EDIM + off] = __float2bfloat16(rn_);
            racc = __fmaf_rn(rn_, rn_, racc);
        } else {
            out[XQ_OFF + (size_t)n * EDIM + off] = x[(size_t)n * EDIM + off] - rn_;
        }
    }
    if (s < 3) {
        racc = warp_tree_reduce(racc);
        if (lane == 0) g_rnorm32[n] = racc;
    }
    #pragma unroll
    for (int off = 16; off; off >>= 1) lsum += __shfl_xor_sync(FULL, lsum, off);
    if (lane == 0) s_ls[w] = lsum;
    __syncthreads();
    if (threadIdx.x == 0) {
        double t = 0.0;
        #pragma unroll
        for (int i = 0; i < 8; i++) t += s_ls[i];
        atomicAdd(&g_loss_arr[s * 64 + (blockIdx.x & 63)], t);
    }
}

__global__ void finalize_kernel(float* __restrict__ out) {
    double t = 0.0;
    for (int i = 0; i < NQ * 64; i++) t += g_loss_arr[i];
    out[LOSS_OFF] = (float)(t * (1.25 / (4.0 * (double)NROWS * (double)EDIM)));
}

// =====================================================================
// Launch: R13 antiphase DAG (proven best)
// =====================================================================
extern "C" void kernel_launch(void* const* d_in, const int* in_sizes, int n_in,
                              void* d_out, int out_size) {
    const float* x  = (const float*)d_in[0];
    const float* cb = (const float*)d_in[1];
    if (n_in >= 2 && in_sizes[0] < in_sizes[1]) { const float* t = x; x = cb; cb = t; }
    float* out = (float*)d_out;

    static cudaStream_t s2 = nullptr;
    static cudaEvent_t evF = nullptr, evJ = nullptr;
    static cudaEvent_t evGA[NQ], evGB[NQ];
    if (s2 == nullptr) {
        cudaStreamCreateWithFlags(&s2, cudaStreamNonBlocking);
        cudaEventCreateWithFlags(&evF, cudaEventDisableTiming);
        cudaEventCreateWithFlags(&evJ, cudaEventDisableTiming);
        for (int i = 0; i < NQ; i++) {
            cudaEventCreateWithFlags(&evGA[i], cudaEventDisableTiming);
            cudaEventCreateWithFlags(&evGB[i], cudaEventDisableTiming);
        }
    }

    cudaFuncSetAttribute(gemm_mma_kernel, cudaFuncAttributeMaxDynamicSharedMemorySize, GM_SMEM);

    prep_kernel<<<(NROWS + NQ * NE) / 8, 256>>>(x, cb);

    // fork
    cudaEventRecord(evF, 0);
    cudaStreamWaitEvent(s2, evF, 0);

    for (int s = 0; s < NQ; s++) {
        if (s > 0) cudaStreamWaitEvent(0, evGB[s - 1], 0);
        gemm_mma_kernel<<<dim3(NE / 128, 256), 256, GM_SMEM, 0>>>(s, 0, out + DIST_OFF);
        cudaEventRecord(evGA[s], 0);
        update_kernel<<<4096, 256, 0, 0>>>(s, 0, x, cb, out);

        cudaStreamWaitEvent(s2, evGA[s], 0);
        gemm_mma_kernel<<<dim3(NE / 128, 256), 256, GM_SMEM, s2>>>(s, 256, out + DIST_OFF);
        cudaEventRecord(evGB[s], 0);
        update_kernel<<<4096, 256, 0, s2>>>(s, 32768, x, cb, out);
    }

    // join
    cudaEventRecord(evJ, s2);
    cudaStreamWaitEvent(0, evJ, 0);
    finalize_kernel<<<1, 1>>>(out);
}

// round 17
// speedup vs baseline: 1.5460x; 1.5460x over previous
#include <cuda_runtime.h>
#include <cuda_bf16.h>
#include <cstdint>
#include <cstddef>

#define NROWS 65536
#define EDIM  512
#define NE    1024
#define NQ    4

static constexpr size_t XQ_OFF   = 0;
static constexpr size_t LOSS_OFF = (size_t)NROWS * EDIM;
static constexpr size_t IDX_OFF  = LOSS_OFF + 1;
static constexpr size_t DIST_OFF = IDX_OFF + (size_t)NROWS * NQ;

// -------- scratch (device globals; no runtime allocation) --------
__device__ float          g_residual[(size_t)NROWS * EDIM];   // valid from stage-0 update on
__device__ __nv_bfloat16  g_res_bf[(size_t)NROWS * EDIM];
__device__ __nv_bfloat16  g_cb_bf[(size_t)NQ * NE * EDIM];
__device__ float          g_enorm32[NQ * NE];   // XLA-GPU-emulated fp32 ||e||^2
__device__ float          g_rnorm32[NROWS];     // XLA-GPU-emulated fp32 ||r||^2 (current stage)
__device__ float          g_top2d[(size_t)NROWS * 16];
__device__ int            g_top2i[(size_t)NROWS * 16];
__device__ double         g_loss_arr[NQ * 64];  // spread loss accumulators

// -------- helpers --------
__device__ __forceinline__ uint32_t s2u(const void* p) {
    uint32_t a;
    asm("{ .reg .u64 t; cvta.to.shared.u64 t, %1; cvt.u32.u64 %0, t; }" : "=r"(a) : "l"(p));
    return a;
}
__device__ __forceinline__ void cpa16_cg(uint32_t daddr, const void* src) {
    asm volatile("cp.async.cg.shared.global [%0], [%1], 16;\n" :: "r"(daddr), "l"(src));
}
__device__ __forceinline__ void ldsm4(uint32_t* r, uint32_t addr) {
    asm volatile("ldmatrix.sync.aligned.m8n8.x4.shared.b16 {%0,%1,%2,%3}, [%4];"
                 : "=r"(r[0]), "=r"(r[1]), "=r"(r[2]), "=r"(r[3]) : "r"(addr));
}
__device__ __forceinline__ void mma16816(float* c, const uint32_t* a, uint32_t b0, uint32_t b1) {
    asm volatile("mma.sync.aligned.m16n8k16.row.col.f32.bf16.bf16.f32 "
                 "{%0,%1,%2,%3}, {%4,%5,%6,%7}, {%8,%9}, {%0,%1,%2,%3};"
                 : "+f"(c[0]), "+f"(c[1]), "+f"(c[2]), "+f"(c[3])
                 : "r"(a[0]), "r"(a[1]), "r"(a[2]), "r"(a[3]), "r"(b0), "r"(b1));
}
__device__ __forceinline__ float warp_tree_reduce(float v) {
    v = __fadd_rn(v, __shfl_down_sync(0xffffffffu, v, 16));
    v = __fadd_rn(v, __shfl_down_sync(0xffffffffu, v, 8));
    v = __fadd_rn(v, __shfl_down_sync(0xffffffffu, v, 4));
    v = __fadd_rn(v, __shfl_down_sync(0xffffffffu, v, 2));
    v = __fadd_rn(v, __shfl_down_sync(0xffffffffu, v, 1));
    return v;
}

// =====================================================================
// prep: bf16 copies + norms (no residual write — residual_0 == x)
// =====================================================================
__global__ void __launch_bounds__(256) prep_kernel(const float* __restrict__ x,
                                                   const float* __restrict__ cb) {
    if (blockIdx.x == 0 && threadIdx.x < NQ * 64) g_loss_arr[threadIdx.x] = 0.0;
    int w = (blockIdx.x * blockDim.x + threadIdx.x) >> 5;
    int lane = threadIdx.x & 31;
    if (w >= NROWS + NQ * NE) return;
    float acc = 0.0f;
    if (w < NROWS) {
        const float* src = x + (size_t)w * EDIM;
        #pragma unroll
        for (int j = 0; j < 16; j++) {
            int off = lane + 32 * j;
            float v = src[off];
            g_res_bf[(size_t)w * EDIM + off] = __float2bfloat16(v);
            acc = __fmaf_rn(v, v, acc);
        }
        acc = warp_tree_reduce(acc);
        if (lane == 0) g_rnorm32[w] = acc;
    } else {
        int c = w - NROWS;
        const float* src = cb + (size_t)c * EDIM;
        #pragma unroll
        for (int j = 0; j < 16; j++) {
            int off = lane + 32 * j;
            float v = src[off];
            g_cb_bf[(size_t)c * EDIM + off] = __float2bfloat16(v);
            acc = __fmaf_rn(v, v, acc);
        }
        acc = warp_tree_reduce(acc);
        if (lane == 0) g_enorm32[c] = acc;
    }
}

// =====================================================================
// mma.sync bf16 GEMM: exact R13/R15 config (byte-identical mainloop+epilogue,
// dist stores get an evict-streaming hint)
// =====================================================================
#define GM_STG   32768
#define GM_SMEM  98304
#define GM_PITCH 129

__global__ void __launch_bounds__(256, 2) gemm_mma_kernel(int s, int yt0, float* __restrict__ dist) {
    extern __shared__ char smem[];
    const uint32_t sb = s2u(smem);
    const int tid = threadIdx.x, wid = tid >> 5, l = tid & 31;
    const int bn0 = blockIdx.x * 128, bm0 = (blockIdx.y + yt0) * 128;
    const int wm = wid >> 2, wn = wid & 3;           // 2x4 warp grid, 64x32 tiles
    const int mbase = wm * 64, nbase = wn * 32;

    const char* Ag = (const char*)(g_res_bf + (size_t)bm0 * EDIM);
    const char* Bg = (const char*)(g_cb_bf + ((size_t)s * NE + bn0) * EDIM);

    const int frow = l & 15;
    const uint32_t fseg = (uint32_t)(l >> 4) * 16;
    const uint32_t mask = (uint32_t)((l & 7) << 4);

    float acc[4][4][4];
    #pragma unroll
    for (int a = 0; a < 4; a++)
        #pragma unroll
        for (int b = 0; b < 4; b++)
            #pragma unroll
            for (int c = 0; c < 4; c++) acc[a][b][c] = 0.0f;

    auto load_chunk = [&](int kc, int stg) {
        uint32_t abase = sb + (uint32_t)stg * GM_STG;
        uint32_t bbase = abase + 16384;
        #pragma unroll
        for (int it = 0; it < 4; it++) {
            int idx = tid + it * 256;
            int r = idx >> 3, c = idx & 7;
            uint32_t soff = (uint32_t)(r * 128 + ((c ^ (r & 7)) * 16));
            cpa16_cg(abase + soff, Ag + (size_t)r * 1024 + (size_t)kc * 128 + c * 16);
            cpa16_cg(bbase + soff, Bg + (size_t)r * 1024 + (size_t)kc * 128 + c * 16);
        }
        asm volatile("cp.async.commit_group;\n");
    };

    load_chunk(0, 0);
    load_chunk(1, 1);

    for (int c = 0; c < 8; c++) {
        int stg = c % 3;
        if (c < 7) asm volatile("cp.async.wait_group 1;\n" ::: "memory");
        else       asm volatile("cp.async.wait_group 0;\n" ::: "memory");
        __syncthreads();
        if (c + 2 < 8) load_chunk(c + 2, (c + 2) % 3);

        uint32_t abase = sb + (uint32_t)stg * GM_STG;
        uint32_t bbase = abase + 16384;
        #pragma unroll
        for (int kk = 0; kk < 4; kk++) {
            uint32_t af[4][4], bf[2][4];
            #pragma unroll
            for (int t = 0; t < 4; t++)
                ldsm4(af[t], abase + (uint32_t)((mbase + t * 16 + frow) * 128)
                              + (((uint32_t)(kk * 32) + fseg) ^ mask));
            #pragma unroll
            for (int p = 0; p < 2; p++)
                ldsm4(bf[p], bbase + (uint32_t)((nbase + p * 16 + frow) * 128)
                              + (((uint32_t)(kk * 32) + fseg) ^ mask));
            #pragma unroll
            for (int tm = 0; tm < 4; tm++)
                #pragma unroll
                for (int p = 0; p < 2; p++) {
                    mma16816(acc[tm][2 * p],     af[tm], bf[p][0], bf[p][2]);
                    mma16816(acc[tm][2 * p + 1], af[tm], bf[p][1], bf[p][3]);
                }
        }
    }
    __syncthreads();

    // ---- single-pass epilogue (exact R13/R15) ----
    float* stage = (float*)smem;                        // 128 x 129 floats (66048 B)
    float* ens   = (float*)(smem + 66048);              // 128 e-norms
    float* rns   = (float*)(smem + 66560);              // 128 r-norms
    float* pd1   = (float*)(smem + 67072);              // 256 partial top-2
    float* pd2   = (float*)(smem + 68096);
    int*   pi1   = (int*)  (smem + 69120);
    int*   pi2   = (int*)  (smem + 70144);
    if (tid < 128) {
        ens[tid] = g_enorm32[s * NE + bn0 + tid];
        rns[tid] = g_rnorm32[bm0 + tid];
    }
    __syncthreads();

    #pragma unroll
    for (int tm = 0; tm < 4; tm++) {
        int r0 = mbase + tm * 16 + (l >> 2);
        float rnA = rns[r0];
        float rnB = rns[r0 + 8];
        #pragma unroll
        for (int tn = 0; tn < 4; tn++) {
            int c0 = nbase + tn * 8 + (l & 3) * 2;
            float e0 = ens[c0], e1 = ens[c0 + 1];
            float* a = acc[tm][tn];
            stage[r0 * GM_PITCH + c0]           = __fadd_rn(__fsub_rn(rnA, __fmul_rn(2.0f, a[0])), e0);
            stage[r0 * GM_PITCH + c0 + 1]       = __fadd_rn(__fsub_rn(rnA, __fmul_rn(2.0f, a[1])), e1);
            stage[(r0 + 8) * GM_PITCH + c0]     = __fadd_rn(__fsub_rn(rnB, __fmul_rn(2.0f, a[2])), e0);
            stage[(r0 + 8) * GM_PITCH + c0 + 1] = __fadd_rn(__fsub_rn(rnB, __fmul_rn(2.0f, a[3])), e1);
        }
    }
    __syncthreads();

    {
        int row = tid & 127, half = tid >> 7;
        float d1 = 3.4e38f, d2 = 3.4e38f; int i1 = 0x7fffffff, i2 = 0x7fffffff;
        int cbase = half * 64;
        #pragma unroll 8
        for (int j = 0; j < 64; j++) {
            float d = stage[row * GM_PITCH + cbase + j];
            int gi = bn0 + cbase + j;
            if (d < d1)      { d2 = d1; i2 = i1; d1 = d; i1 = gi; }
            else if (d < d2) { d2 = d; i2 = gi; }
        }
        pd1[tid] = d1; pd2[tid] = d2; pi1[tid] = i1; pi2[tid] = i2;
    }
    __syncthreads();
    if (tid < 128) {
        float d1a = pd1[tid], d2a = pd2[tid];       int i1a = pi1[tid], i2a = pi2[tid];
        float d1b = pd1[tid + 128], d2b = pd2[tid + 128]; int i1b = pi1[tid + 128], i2b = pi2[tid + 128];
        float m1, m2; int mi1, mi2;
        if (d1b < d1a) {
            m1 = d1b; mi1 = i1b;
            if (d1a <= d2b) { m2 = d1a; mi2 = i1a; } else { m2 = d2b; mi2 = i2b; }
        } else {
            m1 = d1a; mi1 = i1a;
            if (d2a <= d1b) { m2 = d2a; mi2 = i2a; } else { m2 = d1b; mi2 = i1b; }
        }
        int rowG = bm0 + tid;
        size_t tb = ((size_t)rowG * 8 + blockIdx.x) * 2;
        g_top2d[tb] = m1;     g_top2i[tb] = mi1;
        g_top2d[tb + 1] = m2; g_top2i[tb + 1] = mi2;
    }
    // coalesced dist stores (evict-streaming: written once, rarely re-read)
    {
        int rh = tid >> 7, col = tid & 127;
        #pragma unroll 8
        for (int it = 0; it < 64; it++) {
            int r = it * 2 + rh;
            __stcs(&dist[(size_t)(bm0 + r) * (NQ * NE) + (size_t)s * NE + bn0 + col],
                   stage[r * GM_PITCH + col]);
        }
    }
}

// =====================================================================
// argmin refine + bitwise straight-through update (exact R15).
// rrow reads x at s==0 (residual_0 == x bitwise); regs capped at 32 for
// co-residency with gemm (57344 + 8192 = 65536 RF).
// =====================================================================
#define MARGIN 1.25f
#define CANDMAX 32

__global__ void __launch_bounds__(256, 8) update_kernel(int s, int n0, const float* __restrict__ x,
                                                        const float* __restrict__ cb,
                                                        float* __restrict__ out) {
    __shared__ int s_cand[8][CANDMAX];
    __shared__ double s_ls[8];
    const int w = threadIdx.x >> 5, lane = threadIdx.x & 31;
    const int n = n0 + blockIdx.x * 8 + w;
    const unsigned FULL = 0xffffffffu;

    float myd = 3.4e38f; int myi = 0x7fffffff;
    if (lane < 16) { myd = g_top2d[(size_t)n * 16 + lane]; myi = g_top2i[(size_t)n * 16 + lane]; }
    float bd = myd; int bi = myi;
    #pragma unroll
    for (int off = 16; off; off >>= 1) {
        float od = __shfl_xor_sync(FULL, bd, off);
        int   oi = __shfl_xor_sync(FULL, bi, off);
        if (od < bd || (od == bd && oi < bi)) { bd = od; bi = oi; }
    }
    float thr = bd + MARGIN;

    int partner = (lane & 30) | 1;
    float d2b = __shfl_sync(FULL, myd, partner);
    bool block_rescan = (d2b <= thr);
    bool take = (lane < 16) && (myd <= thr) && !block_rescan;
    unsigned tm = __ballot_sync(FULL, take);
    int cnt = __popc(tm);
    if (take) s_cand[w][__popc(tm & ((1u << lane) - 1u))] = myi;

    unsigned rb = __ballot_sync(FULL, (lane < 16) && ((lane & 1) == 1) && (myd <= thr));
    const float* dist = out + DIST_OFF;
    size_t rowbase = (size_t)n * (NQ * NE) + (size_t)s * NE;
    while (rb) {
        int L = __ffs(rb) - 1; rb &= rb - 1;
        int b = L >> 1;
        #pragma unroll
        for (int j = 0; j < 4; j++) {
            int c = b * 128 + lane + 32 * j;
            float dv = dist[rowbase + c];
            bool t2 = (dv <= thr);
            unsigned m2 = __ballot_sync(FULL, t2);
            if (t2) {
                int pos = cnt + __popc(m2 & ((1u << lane) - 1u));
                if (pos < CANDMAX) s_cand[w][pos] = c;
            }
            cnt += __popc(m2);
        }
    }
    if (cnt > CANDMAX) cnt = CANDMAX;
    __syncwarp();

    const float* rrow = (s == 0) ? (x + (size_t)n * EDIM)
                                 : (g_residual + (size_t)n * EDIM);
    int chosen;
    if (cnt == 1) {
        chosen = bi;
    } else {
        float a = g_rnorm32[n];
        int myc = (lane < cnt) ? s_cand[w][lane] : -1;
        float dmy = 3.4e38f;
        if (myc >= 0) {
            const float* e = cb + ((size_t)s * NE + myc) * EDIM;
            float b = 0.0f;
            for (int k = 0; k < EDIM; k++) b = __fmaf_rn(rrow[k], e[k], b);
            dmy = __fadd_rn(__fsub_rn(a, __fmul_rn(2.0f, b)), g_enorm32[s * NE + myc]);
        }
        float cbd = dmy; int cbi = (myc >= 0) ? myc : 0x7fffffff;
        #pragma unroll
        for (int off = 16; off; off >>= 1) {
            float od = __shfl_xor_sync(FULL, cbd, off);
            int   oi = __shfl_xor_sync(FULL, cbi, off);
            if (od < cbd || (od == cbd && oi < cbi)) { cbd = od; cbi = oi; }
        }
        chosen = cbi;
    }
    if (lane == 0) out[IDX_OFF + (size_t)n * NQ + s] = (float)chosen;

    const float* e = cb + ((size_t)s * NE + chosen) * EDIM;
    double lsum = 0.0;
    float racc = 0.0f;
    #pragma unroll 4
    for (int j = 0; j < 16; j++) {
        int off = lane + 32 * j;
        float r  = rrow[off];
        float ev = e[off];
        float u     = __fsub_rn(ev, r);      // xq - residual
        float xq_st = __fadd_rn(r, u);       // residual + (xq - residual)
        float rn_   = __fsub_rn(r, xq_st);   // new residual
        lsum += (double)u * (double)u;
        if (s < 3) {
            g_residual[(size_t)n * EDIM + off] = rn_;
            g_res_bf[(size_t)n * EDIM + off] = __float2bfloat16(rn_);
            racc = __fmaf_rn(rn_, rn_, racc);
        } else {
            __stcs(&out[XQ_OFF + (size_t)n * EDIM + off],
                   x[(size_t)n * EDIM + off] - rn_);
        }
    }
    if (s < 3) {
        racc = warp_tree_reduce(racc);
        if (lane == 0) g_rnorm32[n] = racc;
    }
    #pragma unroll
    for (int off = 16; off; off >>= 1) lsum += __shfl_xor_sync(FULL, lsum, off);
    if (lane == 0) s_ls[w] = lsum;
    __syncthreads();
    if (threadIdx.x == 0) {
        double t = 0.0;
        #pragma unroll
        for (int i = 0; i < 8; i++) t += s_ls[i];
        atomicAdd(&g_loss_arr[s * 64 + (blockIdx.x & 63)], t);
    }
}

__global__ void finalize_kernel(float* __restrict__ out) {
    double t = 0.0;
    for (int i = 0; i < NQ * 64; i++) t += g_loss_arr[i];
    out[LOSS_OFF] = (float)(t * (1.25 / (4.0 * (double)NROWS * (double)EDIM)));
}

// =====================================================================
// Launch: R13 antiphase DAG (proven best)
// =====================================================================
extern "C" void kernel_launch(void* const* d_in, const int* in_sizes, int n_in,
                              void* d_out, int out_size) {
    const float* x  = (const float*)d_in[0];
    const float* cb = (const float*)d_in[1];
    if (n_in >= 2 && in_sizes[0] < in_sizes[1]) { const float* t = x; x = cb; cb = t; }
    float* out = (float*)d_out;

    static cudaStream_t s2 = nullptr;
    static cudaEvent_t evF = nullptr, evJ = nullptr;
    static cudaEvent_t evGA[NQ], evGB[NQ];
    if (s2 == nullptr) {
        cudaStreamCreateWithFlags(&s2, cudaStreamNonBlocking);
        cudaEventCreateWithFlags(&evF, cudaEventDisableTiming);
        cudaEventCreateWithFlags(&evJ, cudaEventDisableTiming);
        for (int i = 0; i < NQ; i++) {
            cudaEventCreateWithFlags(&evGA[i], cudaEventDisableTiming);
            cudaEventCreateWithFlags(&evGB[i], cudaEventDisableTiming);
        }
    }

    cudaFuncSetAttribute(gemm_mma_kernel, cudaFuncAttributeMaxDynamicSharedMemorySize, GM_SMEM);

    prep_kernel<<<(NROWS + NQ * NE) / 8, 256>>>(x, cb);

    // fork
    cudaEventRecord(evF, 0);
    cudaStreamWaitEvent(s2, evF, 0);

    for (int s = 0; s < NQ; s++) {
        if (s > 0) cudaStreamWaitEvent(0, evGB[s - 1], 0);
        gemm_mma_kernel<<<dim3(NE / 128, 256), 256, GM_SMEM, 0>>>(s, 0, out + DIST_OFF);
        cudaEventRecord(evGA[s], 0);
        update_kernel<<<4096, 256, 0, 0>>>(s, 0, x, cb, out);

        cudaStreamWaitEvent(s2, evGA[s], 0);
        gemm_mma_kernel<<<dim3(NE / 128, 256), 256, GM_SMEM, s2>>>(s, 256, out + DIST_OFF);
        cudaEventRecord(evGB[s], 0);
        update_kernel<<<4096, 256, 0, s2>>>(s, 32768, x, cb, out);
    }

    // join
    cudaEventRecord(evJ, s2);
    cudaStreamWaitEvent(0, evJ, 0);
    finalize_kernel<<<1, 1>>>(out);
}